// round 9
// baseline (speedup 1.0000x reference)
#include <cuda_runtime.h>
#include <cuda_bf16.h>
#include <cuda_pipeline.h>
#include <cstdint>

// Problem constants (fixed shapes)
#define NIMG 28           // B*T pairs = 4*7
#define HW   4096         // 64*64
#define PP   441          // 21*21
#define NTOT (NIMG*HW)    // elements per displacement = 114688
#define KPAD 448          // padded K for GEMM

// ---------------- device scratch ----------------
__device__ float g_cor[(size_t)NIMG * PP * HW + 7 * HW];  // pad 7 rows for K=448 reads
__device__ float g_parts [PP * 112];
__device__ float g_partsq[PP * 112];
__device__ float g_scale[PP];
__device__ float g_shift[PP];
__device__ float g_w2d[KPAD * 128];                // [p][2o] duplicated pairs, zero-padded
__device__ float g_bias[64];

// ---------------- f32x2 helpers ----------------
typedef unsigned long long ull;
__device__ __forceinline__ ull f32x2_pack(float x, float y) {
    ull r; asm("mov.b64 %0, {%1, %2};" : "=l"(r) : "f"(x), "f"(y)); return r;
}
__device__ __forceinline__ void f32x2_fma(ull& d, ull a, ull b) {
    asm("fma.rn.f32x2 %0, %1, %2, %0;" : "+l"(d) : "l"(a), "l"(b));
}
__device__ __forceinline__ float2 f32x2_unpack(ull v) {
    float2 r; asm("mov.b64 {%0, %1}, %2;" : "=f"(r.x), "=f"(r.y) : "l"(v)); return r;
}

// =======================================================================
// Kernel 1: correlation + fused BN-stat partials.
// cor[n, dy*21+dx, h, w] = sum_c f1[n,c,h,w] * f2[n,c, h+2dy-20, w+2dx-20]
// Grid (4 htiles, 28 n, 21 dy).  Block 128 = 16 r x 8 g; thread owns 8 w.
// f2 rows staged in smem (row stride 108 floats -> LDS.128 conflict-free:
// 16B-chunk stride 27 is odd), channel chunks of 4, cp.async double buffer.
// Window loaded as 12 LDS.128 -> 24 f32x2 operands; all math f32x2.
// =======================================================================
#define CCH 4
#define ROWF 108                       // smem floats per staged row
#define STAGEF (CCH * 16 * ROWF)       // 6912 floats per buffer
#define CORR_SMEM_BYTES (2 * STAGEF * 4)   // 55296

__global__ void __launch_bounds__(128, 2) corr_kernel(const float* __restrict__ feats) {
    extern __shared__ float sm[];
    const int h0 = blockIdx.x * 16;
    const int n  = blockIdx.y;
    const int dy = blockIdx.z;
    const int b  = n / 7, t = n % 7;
    const int d  = 2 * dy - 20;

    const int tid = threadIdx.x;
    const int r   = tid & 15;          // row in tile
    const int g   = tid >> 4;          // 0..7, owns w = 8g..8g+7

    const float* f1p    = feats + (size_t)(b * 8 + t) * 64 * HW + (h0 + r) * 64 + 8 * g;
    const float* f2base = feats + (size_t)(b * 8 + t + 1) * 64 * HW;

    // zero both stage buffers once (OOB rows/cols stay zero; fills only
    // overwrite the valid region, identical pattern across channel chunks)
    for (int i = tid; i < 2 * STAGEF; i += 128) sm[i] = 0.f;
    __syncthreads();

    auto fill = [&](int s, int buf) {
        const int c0 = s * CCH;
        float* dstb = sm + buf * STAGEF;
#pragma unroll
        for (int it = 0; it < 8; it++) {
            int idx = tid + it * 128;           // < 1024
            int ci  = idx >> 8;
            int rr  = (idx >> 4) & 15;
            int k   = (idx & 15) + 5;           // scol 4k covers gcol 0..63
            int grow = h0 + rr + d;
            if ((unsigned)grow < 64u) {
                __pipeline_memcpy_async(dstb + (ci * 16 + rr) * ROWF + 4 * k,
                    f2base + (size_t)(c0 + ci) * HW + grow * 64 + (4 * k - 20), 16);
            }
        }
    };

    fill(0, 0);
    __pipeline_commit();

    ull acc[21][4];
#pragma unroll
    for (int px = 0; px < 21; px++)
#pragma unroll
        for (int q = 0; q < 4; q++) acc[px][q] = 0ull;

    for (int s = 0; s < 16; s++) {
        const int buf = s & 1;
        if (s + 1 < 16) { fill(s + 1, buf ^ 1); __pipeline_commit(); }
        if (s + 1 < 16) __pipeline_wait_prior(1); else __pipeline_wait_prior(0);
        __syncthreads();

        const int c0 = s * CCH;
        const float* f1c = f1p + (size_t)c0 * HW;
        const float* wb  = sm + buf * STAGEF + r * ROWF + 8 * g;

#pragma unroll
        for (int ci = 0; ci < CCH; ci++) {
            const float4 a  = *(const float4*)(f1c + (size_t)ci * HW);
            const float4 b4 = *(const float4*)(f1c + (size_t)ci * HW + 4);
            const ull p01 = f32x2_pack(a.x,  a.y);
            const ull p23 = f32x2_pack(a.z,  a.w);
            const ull p45 = f32x2_pack(b4.x, b4.y);
            const ull p67 = f32x2_pack(b4.z, b4.w);

            const float* w = wb + ci * (16 * ROWF);
            __align__(16) ull w2[24];
#pragma unroll
            for (int j = 0; j < 12; j++) {
                *(float4*)&w2[2 * j] = *(const float4*)(w + 4 * j);
            }
#pragma unroll
            for (int dx = 0; dx < 21; dx++) {
                f32x2_fma(acc[dx][0], p01, w2[dx]);
                f32x2_fma(acc[dx][1], p23, w2[dx + 1]);
                f32x2_fma(acc[dx][2], p45, w2[dx + 2]);
                f32x2_fma(acc[dx][3], p67, w2[dx + 3]);
            }
        }
        __syncthreads();   // all reads of buf done before it is refilled
    }

    // ---- store 21 x 8 floats ----
    float* dst0 = g_cor + ((size_t)n * PP + (size_t)dy * 21) * HW + (h0 + r) * 64 + 8 * g;
#pragma unroll
    for (int dx = 0; dx < 21; dx++) {
        *(ulonglong2*)(dst0 + (size_t)dx * HW)     = make_ulonglong2(acc[dx][0], acc[dx][1]);
        *(ulonglong2*)(dst0 + (size_t)dx * HW + 4) = make_ulonglong2(acc[dx][2], acc[dx][3]);
    }

    // ---- fused stat partials: per-p sum / sumsq over this block's 1024 px ----
    __syncthreads();   // smem free for reduction
#pragma unroll
    for (int dx = 0; dx < 21; dx++) {
        float s = 0.f, q = 0.f;
#pragma unroll
        for (int k = 0; k < 4; k++) {
            float2 v = f32x2_unpack(acc[dx][k]);
            s += v.x + v.y;
            q += v.x * v.x + v.y * v.y;
        }
        sm[dx * 128 + tid]        = s;
        sm[(21 + dx) * 128 + tid] = q;
    }
    __syncthreads();
    if (tid < 42) {
        float v = 0.f;
        const float* row = sm + tid * 128;
#pragma unroll 8
        for (int i = 0; i < 128; i++) v += row[i];
        const int px = (tid < 21) ? tid : tid - 21;
        const int p  = dy * 21 + px;
        const int bi = blockIdx.x * 28 + n;     // 0..111
        if (tid < 21) g_parts[p * 112 + bi] = v;
        else          g_partsq[p * 112 + bi] = v;
    }
}

// =======================================================================
// Kernel 2: finish stats -> scale/shift
// =======================================================================
__global__ void __launch_bounds__(448) stats2_kernel(const float* __restrict__ gamma,
                                                     const float* __restrict__ beta) {
    const int p = threadIdx.x;
    if (p >= PP) return;
    float s = 0.f, q = 0.f;
    const float* ps = g_parts  + p * 112;
    const float* pq = g_partsq + p * 112;
#pragma unroll 8
    for (int i = 0; i < 112; i++) { s += ps[i]; q += pq[i]; }
    const float inv = 1.0f / (float)NTOT;
    float mean = s * inv;
    float var  = q * inv - mean * mean;
    float sc   = gamma[p] * rsqrtf(var + 1e-5f);
    g_scale[p] = sc;
    g_shift[p] = beta[p] - mean * sc;
}

// =======================================================================
// Kernel 3: fold scale into transposed+DUPLICATED weights + bias
// g_w2d[p][2o] = g_w2d[p][2o+1] = w[o][p]*scale[p];  pad rows 441..447 = 0
// =======================================================================
__global__ void __launch_bounds__(256) prep_kernel(const float* __restrict__ conv_w) {
    const int o = blockIdx.x;
    const int tid = threadIdx.x;
    float bsum = 0.f;
    for (int p = tid; p < PP; p += 256) {
        float w = conv_w[o * PP + p];
        float v = w * g_scale[p];
        g_w2d[p * 128 + 2 * o]     = v;
        g_w2d[p * 128 + 2 * o + 1] = v;
        bsum += w * g_shift[p];
    }
    if (tid < KPAD - PP) {   // 7 pad rows; blockIdx covers both dup slots of o
        g_w2d[(PP + tid) * 128 + 2 * o]     = 0.f;
        g_w2d[(PP + tid) * 128 + 2 * o + 1] = 0.f;
    }
    __shared__ float rb[8];
#pragma unroll
    for (int off = 16; off > 0; off >>= 1) bsum += __shfl_down_sync(0xffffffffu, bsum, off);
    if ((tid & 31) == 0) rb[tid >> 5] = bsum;
    __syncthreads();
    if (tid == 0) {
        float tb = 0.f;
#pragma unroll
        for (int i = 0; i < 8; i++) tb += rb[i];
        g_bias[o] = tb;
    }
}

// =======================================================================
// Kernel 4: GEMM  out[n,o,hw] = sum_p w2t[p][o]*cor[n,p,hw] + bias[o]
// Block: 64 o x 256 hw, 256 thr = 8 og x 32 hwg; thread tile 8o x 8hw.
// A-operands come pre-duplicated from smem (broadcast LDS.128, no dup movs).
// K padded to 448 = 56 chunks of 8, cp.async double buffered.
// =======================================================================
#define KC 8

__global__ void __launch_bounds__(256, 1) gemm_kernel(float* __restrict__ out) {
    __shared__ float cs[2][KC][256];
    __shared__ float ws[2][KC][128];

    const int hw0 = blockIdx.x * 256;
    const int n   = blockIdx.y;
    const int fo  = (n / 7) * 8 + (n % 7);

    const int tid = threadIdx.x;
    const int og  = tid >> 5;       // 0..7 -> o = 8og..8og+7
    const int hwg = tid & 31;       // 0..31 -> hw = hwg*8..hwg*8+7

    const float* corn = g_cor + (size_t)n * PP * HW;

    auto fill = [&](int s, int buf) {
        const int k0 = s * KC;
#pragma unroll
        for (int it = 0; it < 2; it++) {
            int idx = tid + it * 256;          // < 512 : 8 k-rows x 64 float4
            int kk  = idx >> 6;
            int c4  = idx & 63;
            __pipeline_memcpy_async(&cs[buf][kk][4 * c4],
                corn + (size_t)(k0 + kk) * HW + hw0 + 4 * c4, 16);
        }
        {
            int kk = tid >> 5;                 // 256 thr : 8 k-rows x 32 float4
            int c4 = tid & 31;
            __pipeline_memcpy_async(&ws[buf][kk][4 * c4],
                g_w2d + (size_t)(k0 + kk) * 128 + 4 * c4, 16);
        }
    };

    ull acc[8][4];
#pragma unroll
    for (int o = 0; o < 8; o++)
#pragma unroll
        for (int q = 0; q < 4; q++) acc[o][q] = 0ull;

    fill(0, 0);
    __pipeline_commit();

    const int NS = KPAD / KC;   // 56
    for (int s = 0; s < NS; s++) {
        const int buf = s & 1;
        if (s + 1 < NS) { fill(s + 1, buf ^ 1); __pipeline_commit(); }
        if (s + 1 < NS) __pipeline_wait_prior(1); else __pipeline_wait_prior(0);
        __syncthreads();

#pragma unroll
        for (int kk = 0; kk < KC; kk++) {
            __align__(16) ull ad[8];
            *(float4*)&ad[0] = *(const float4*)&ws[buf][kk][og * 16];       // dup pairs o..o+3
            *(float4*)&ad[2] = *(const float4*)&ws[buf][kk][og * 16 + 4];
            *(float4*)&ad[4] = *(const float4*)&ws[buf][kk][og * 16 + 8];
            *(float4*)&ad[6] = *(const float4*)&ws[buf][kk][og * 16 + 12];
            __align__(16) ull bb[4];
            *(float4*)&bb[0] = *(const float4*)&cs[buf][kk][hwg * 8];
            *(float4*)&bb[2] = *(const float4*)&cs[buf][kk][hwg * 8 + 4];
#pragma unroll
            for (int o = 0; o < 8; o++) {
                f32x2_fma(acc[o][0], ad[o], bb[0]);
                f32x2_fma(acc[o][1], ad[o], bb[1]);
                f32x2_fma(acc[o][2], ad[o], bb[2]);
                f32x2_fma(acc[o][3], ad[o], bb[3]);
            }
        }
        __syncthreads();
    }

    float* outn = out + (size_t)fo * 64 * HW;
#pragma unroll
    for (int o = 0; o < 8; o++) {
        const int oo = og * 8 + o;
        const float bv = g_bias[oo];
        float2 p0 = f32x2_unpack(acc[o][0]);
        float2 p1 = f32x2_unpack(acc[o][1]);
        float2 p2 = f32x2_unpack(acc[o][2]);
        float2 p3 = f32x2_unpack(acc[o][3]);
        float* dst = outn + (size_t)oo * HW + hw0 + hwg * 8;
        *(float4*)(dst)     = make_float4(p0.x + bv, p0.y + bv, p1.x + bv, p1.y + bv);
        *(float4*)(dst + 4) = make_float4(p2.x + bv, p2.y + bv, p3.x + bv, p3.y + bv);
    }
}

// =======================================================================
extern "C" void kernel_launch(void* const* d_in, const int* in_sizes, int n_in,
                              void* d_out, int out_size) {
    const float* feats  = (const float*)d_in[0];   // [4,8,64,64,64]
    const float* gamma  = (const float*)d_in[1];   // [441]
    const float* beta   = (const float*)d_in[2];   // [441]
    const float* conv_w = (const float*)d_in[3];   // [64,441]
    float* out = (float*)d_out;                    // [4,8,64,64,64]

    cudaFuncSetAttribute(corr_kernel, cudaFuncAttributeMaxDynamicSharedMemorySize,
                         CORR_SMEM_BYTES);

    // 5 memsets FIRST (zero frame t=7 per batch; first frame split in two)
    // so corr_kernel is launch #6 and gets captured by ncu (-s 5 -c 1).
    const size_t frame = (size_t)64 * HW;
    cudaMemsetAsync(out + (size_t)7 * frame, 0, frame * sizeof(float) / 2);
    cudaMemsetAsync(out + (size_t)7 * frame + frame / 2, 0, frame * sizeof(float) / 2);
    for (int b = 1; b < 4; b++) {
        cudaMemsetAsync(out + ((size_t)(b * 8 + 7)) * frame, 0, frame * sizeof(float));
    }

    corr_kernel<<<dim3(4, 28, 21), 128, CORR_SMEM_BYTES>>>(feats);
    stats2_kernel<<<1, 448>>>(gamma, beta);
    prep_kernel<<<64, 256>>>(conv_w);
    gemm_kernel<<<dim3(16, 28), 256>>>(out);
}

// round 10
// speedup vs baseline: 1.1251x; 1.1251x over previous
#include <cuda_runtime.h>
#include <cuda_bf16.h>
#include <cuda_pipeline.h>
#include <cstdint>

// Problem constants (fixed shapes)
#define NIMG 28           // B*T pairs = 4*7
#define HW   4096         // 64*64
#define PP   441          // 21*21
#define NTOT (NIMG*HW)    // elements per displacement = 114688
#define KPAD 448          // padded K for GEMM

// ---------------- device scratch ----------------
__device__ float g_cor[(size_t)NIMG * PP * HW + 7 * HW];  // pad 7 rows for K=448 reads
__device__ float g_parts [PP * 112];
__device__ float g_partsq[PP * 112];
__device__ float g_scale[PP];
__device__ float g_shift[PP];
__device__ float g_w2t[KPAD * 64];                 // [p][o], scale folded, zero-padded
__device__ float g_bias[64];

// ---------------- f32x2 helpers ----------------
typedef unsigned long long ull;
__device__ __forceinline__ ull f32x2_dup(float x) {
    ull r; asm("mov.b64 %0, {%1, %1};" : "=l"(r) : "f"(x)); return r;
}
__device__ __forceinline__ ull f32x2_pack(float x, float y) {
    ull r; asm("mov.b64 %0, {%1, %2};" : "=l"(r) : "f"(x), "f"(y)); return r;
}
__device__ __forceinline__ void f32x2_fma(ull& d, ull a, ull b) {
    asm("fma.rn.f32x2 %0, %1, %2, %0;" : "+l"(d) : "l"(a), "l"(b));
}
__device__ __forceinline__ float2 f32x2_unpack(ull v) {
    float2 r; asm("mov.b64 {%0, %1}, %2;" : "=f"(r.x), "=f"(r.y) : "l"(v)); return r;
}

// =======================================================================
// Kernel 1: correlation + fused BN-stat partials.
// cor[n, dy*21+dx, h, w] = sum_c f1[n,c,h,w] * f2[n,c, h+2dy-20, w+2dx-20]
// Grid (4 htiles, 28 n, 21 dy).  Block 128 = 16 r x 8 g; thread owns 8 w.
// f2 staged in smem (row stride 108 floats -> LDS.128 conflict-free),
// channel chunks of 4, cp.async double buffer.  f1 is software-pipelined
// through a distance-4 register ring (slot index == ci, compile-time).
// =======================================================================
#define CCH 4
#define ROWF 108                       // smem floats per staged row
#define STAGEF (CCH * 16 * ROWF)       // 6912 floats per buffer
#define CORR_SMEM_BYTES (2 * STAGEF * 4)   // 55296

__global__ void __launch_bounds__(128, 2) corr_kernel(const float* __restrict__ feats) {
    extern __shared__ float sm[];
    const int h0 = blockIdx.x * 16;
    const int n  = blockIdx.y;
    const int dy = blockIdx.z;
    const int b  = n / 7, t = n % 7;
    const int d  = 2 * dy - 20;

    const int tid = threadIdx.x;
    const int r   = tid & 15;          // row in tile
    const int g   = tid >> 4;          // 0..7, owns w = 8g..8g+7

    const float* f1p    = feats + (size_t)(b * 8 + t) * 64 * HW + (h0 + r) * 64 + 8 * g;
    const float* f2base = feats + (size_t)(b * 8 + t + 1) * 64 * HW;

    // zero both stage buffers once (OOB rows/cols stay zero; fills only
    // overwrite the valid region, identical pattern across channel chunks)
    for (int i = tid; i < 2 * STAGEF; i += 128) sm[i] = 0.f;
    __syncthreads();

    auto fill = [&](int s, int buf) {
        const int c0 = s * CCH;
        float* dstb = sm + buf * STAGEF;
#pragma unroll
        for (int it = 0; it < 8; it++) {
            int idx = tid + it * 128;           // < 1024
            int ci  = idx >> 8;
            int rr  = (idx >> 4) & 15;
            int k   = (idx & 15) + 5;           // scol 4k covers gcol 0..63
            int grow = h0 + rr + d;
            if ((unsigned)grow < 64u) {
                __pipeline_memcpy_async(dstb + (ci * 16 + rr) * ROWF + 4 * k,
                    f2base + (size_t)(c0 + ci) * HW + grow * 64 + (4 * k - 20), 16);
            }
        }
    };

    fill(0, 0);
    __pipeline_commit();

    // f1 register ring: slot ci holds channel c = 4s+ci
    float4 f1r[CCH][2];
#pragma unroll
    for (int ci = 0; ci < CCH; ci++) {
        f1r[ci][0] = *(const float4*)(f1p + (size_t)ci * HW);
        f1r[ci][1] = *(const float4*)(f1p + (size_t)ci * HW + 4);
    }

    ull acc[21][4];
#pragma unroll
    for (int px = 0; px < 21; px++)
#pragma unroll
        for (int q = 0; q < 4; q++) acc[px][q] = 0ull;

    for (int s = 0; s < 16; s++) {
        const int buf = s & 1;
        if (s + 1 < 16) { fill(s + 1, buf ^ 1); __pipeline_commit(); }
        if (s + 1 < 16) __pipeline_wait_prior(1); else __pipeline_wait_prior(0);
        __syncthreads();

        const float* wb = sm + buf * STAGEF + r * ROWF + 8 * g;

#pragma unroll
        for (int ci = 0; ci < CCH; ci++) {
            const int c = 4 * s + ci;
            // issue next-round f1 loads early (distance 4 channels ~ 500 cyc)
            float4 n0, n1;
            const bool pf = (c + 4 < 64);
            if (pf) {
                n0 = *(const float4*)(f1p + (size_t)(c + 4) * HW);
                n1 = *(const float4*)(f1p + (size_t)(c + 4) * HW + 4);
            }

            const float4 a  = f1r[ci][0];
            const float4 b4 = f1r[ci][1];
            const ull p01 = f32x2_pack(a.x,  a.y);
            const ull p23 = f32x2_pack(a.z,  a.w);
            const ull p45 = f32x2_pack(b4.x, b4.y);
            const ull p67 = f32x2_pack(b4.z, b4.w);

            const float* w = wb + ci * (16 * ROWF);
            __align__(16) ull w2[24];
#pragma unroll
            for (int j = 0; j < 12; j++) {
                *(float4*)&w2[2 * j] = *(const float4*)(w + 4 * j);
            }
#pragma unroll
            for (int dx = 0; dx < 21; dx++) {
                f32x2_fma(acc[dx][0], p01, w2[dx]);
                f32x2_fma(acc[dx][1], p23, w2[dx + 1]);
                f32x2_fma(acc[dx][2], p45, w2[dx + 2]);
                f32x2_fma(acc[dx][3], p67, w2[dx + 3]);
            }

            if (pf) { f1r[ci][0] = n0; f1r[ci][1] = n1; }
        }
        __syncthreads();   // all reads of buf done before it is refilled
    }

    // ---- store 21 x 8 floats ----
    float* dst0 = g_cor + ((size_t)n * PP + (size_t)dy * 21) * HW + (h0 + r) * 64 + 8 * g;
#pragma unroll
    for (int dx = 0; dx < 21; dx++) {
        *(ulonglong2*)(dst0 + (size_t)dx * HW)     = make_ulonglong2(acc[dx][0], acc[dx][1]);
        *(ulonglong2*)(dst0 + (size_t)dx * HW + 4) = make_ulonglong2(acc[dx][2], acc[dx][3]);
    }

    // ---- fused stat partials: per-p sum / sumsq over this block's 1024 px ----
    __syncthreads();   // smem free for reduction
#pragma unroll
    for (int dx = 0; dx < 21; dx++) {
        float s = 0.f, q = 0.f;
#pragma unroll
        for (int k = 0; k < 4; k++) {
            float2 v = f32x2_unpack(acc[dx][k]);
            s += v.x + v.y;
            q += v.x * v.x + v.y * v.y;
        }
        sm[dx * 128 + tid]        = s;
        sm[(21 + dx) * 128 + tid] = q;
    }
    __syncthreads();
    if (tid < 42) {
        float v = 0.f;
        const float* row = sm + tid * 128;
#pragma unroll 8
        for (int i = 0; i < 128; i++) v += row[i];
        const int px = (tid < 21) ? tid : tid - 21;
        const int p  = dy * 21 + px;
        const int bi = blockIdx.x * 28 + n;     // 0..111
        if (tid < 21) g_parts[p * 112 + bi] = v;
        else          g_partsq[p * 112 + bi] = v;
    }
}

// =======================================================================
// Kernel 2: finish stats -> scale/shift
// =======================================================================
__global__ void __launch_bounds__(448) stats2_kernel(const float* __restrict__ gamma,
                                                     const float* __restrict__ beta) {
    const int p = threadIdx.x;
    if (p >= PP) return;
    float s = 0.f, q = 0.f;
    const float* ps = g_parts  + p * 112;
    const float* pq = g_partsq + p * 112;
#pragma unroll 8
    for (int i = 0; i < 112; i++) { s += ps[i]; q += pq[i]; }
    const float inv = 1.0f / (float)NTOT;
    float mean = s * inv;
    float var  = q * inv - mean * mean;
    float sc   = gamma[p] * rsqrtf(var + 1e-5f);
    g_scale[p] = sc;
    g_shift[p] = beta[p] - mean * sc;
}

// =======================================================================
// Kernel 3: fold scale into transposed weights + bias, zero-pad K to 448
// =======================================================================
__global__ void __launch_bounds__(256) prep_kernel(const float* __restrict__ conv_w) {
    const int o = blockIdx.x;
    const int tid = threadIdx.x;
    float bsum = 0.f;
    for (int p = tid; p < PP; p += 256) {
        float w = conv_w[o * PP + p];
        g_w2t[p * 64 + o] = w * g_scale[p];
        bsum += w * g_shift[p];
    }
    if (tid < KPAD - PP) g_w2t[(PP + tid) * 64 + o] = 0.f;
    __shared__ float rb[8];
#pragma unroll
    for (int off = 16; off > 0; off >>= 1) bsum += __shfl_down_sync(0xffffffffu, bsum, off);
    if ((tid & 31) == 0) rb[tid >> 5] = bsum;
    __syncthreads();
    if (tid == 0) {
        float tb = 0.f;
#pragma unroll
        for (int i = 0; i < 8; i++) tb += rb[i];
        g_bias[o] = tb;
    }
}

// =======================================================================
// Kernel 4: GEMM  out[n,o,hw] = sum_p w2t[p][o]*cor[n,p,hw] + bias[o]
// Block: 64 o x 128 hw, 256 thr = 8 og x 32 hwg (warp == one og -> w broadcast).
// K padded to 448 = 28 chunks of 16, cp.async double buffered.
// (R5 configuration, measured 118us.)
// =======================================================================
#define KC 16

__global__ void __launch_bounds__(256, 2) gemm_kernel(float* __restrict__ out) {
    __shared__ float cs[2][KC][128];
    __shared__ float ws[2][KC][64];

    const int hw0 = blockIdx.x * 128;
    const int n   = blockIdx.y;
    const int fo  = (n / 7) * 8 + (n % 7);

    const int tid = threadIdx.x;
    const int og  = tid >> 5;
    const int hwg = tid & 31;

    const float* corn = g_cor + (size_t)n * PP * HW;

    auto fill = [&](int s, int buf) {
        const int k0 = s * KC;
#pragma unroll
        for (int it = 0; it < 2; it++) {
            int idx = tid + it * 256;          // < 512 : 16 k-rows x 32 float4
            int kk  = idx >> 5;
            int c4  = idx & 31;
            __pipeline_memcpy_async(&cs[buf][kk][4 * c4],
                corn + (size_t)(k0 + kk) * HW + hw0 + 4 * c4, 16);
        }
        {
            int kk = tid >> 4;                 // 256 thr : 16 k-rows x 16 float4
            int c4 = tid & 15;
            __pipeline_memcpy_async(&ws[buf][kk][4 * c4],
                g_w2t + (size_t)(k0 + kk) * 64 + 4 * c4, 16);
        }
    };

    ull acc[8][2];
#pragma unroll
    for (int o = 0; o < 8; o++) { acc[o][0] = 0ull; acc[o][1] = 0ull; }

    fill(0, 0);
    __pipeline_commit();

    const int NS = KPAD / KC;   // 28
    for (int s = 0; s < NS; s++) {
        const int buf = s & 1;
        if (s + 1 < NS) { fill(s + 1, buf ^ 1); __pipeline_commit(); }
        if (s + 1 < NS) __pipeline_wait_prior(1); else __pipeline_wait_prior(0);
        __syncthreads();

#pragma unroll
        for (int kk = 0; kk < KC; kk++) {
            const float4 w0 = *(const float4*)&ws[buf][kk][og * 8];
            const float4 w1 = *(const float4*)&ws[buf][kk][og * 8 + 4];
            const ulonglong2 bb = *(const ulonglong2*)&cs[buf][kk][hwg * 4];
            ull ad[8];
            ad[0] = f32x2_dup(w0.x); ad[1] = f32x2_dup(w0.y);
            ad[2] = f32x2_dup(w0.z); ad[3] = f32x2_dup(w0.w);
            ad[4] = f32x2_dup(w1.x); ad[5] = f32x2_dup(w1.y);
            ad[6] = f32x2_dup(w1.z); ad[7] = f32x2_dup(w1.w);
#pragma unroll
            for (int o = 0; o < 8; o++) {
                f32x2_fma(acc[o][0], ad[o], bb.x);
                f32x2_fma(acc[o][1], ad[o], bb.y);
            }
        }
        __syncthreads();
    }

    float* outn = out + (size_t)fo * 64 * HW;
#pragma unroll
    for (int o = 0; o < 8; o++) {
        const int oo = og * 8 + o;
        const float bv = g_bias[oo];
        float2 p0 = f32x2_unpack(acc[o][0]);
        float2 p1 = f32x2_unpack(acc[o][1]);
        *(float4*)(outn + (size_t)oo * HW + hw0 + hwg * 4) =
            make_float4(p0.x + bv, p0.y + bv, p1.x + bv, p1.y + bv);
    }
}

// =======================================================================
extern "C" void kernel_launch(void* const* d_in, const int* in_sizes, int n_in,
                              void* d_out, int out_size) {
    const float* feats  = (const float*)d_in[0];   // [4,8,64,64,64]
    const float* gamma  = (const float*)d_in[1];   // [441]
    const float* beta   = (const float*)d_in[2];   // [441]
    const float* conv_w = (const float*)d_in[3];   // [64,441]
    float* out = (float*)d_out;                    // [4,8,64,64,64]

    cudaFuncSetAttribute(corr_kernel, cudaFuncAttributeMaxDynamicSharedMemorySize,
                         CORR_SMEM_BYTES);

    corr_kernel<<<dim3(4, 28, 21), 128, CORR_SMEM_BYTES>>>(feats);
    stats2_kernel<<<1, 448>>>(gamma, beta);
    prep_kernel<<<64, 256>>>(conv_w);
    gemm_kernel<<<dim3(32, 28), 256>>>(out);

    // zero frame t=7 for each batch
    const size_t frame = (size_t)64 * HW;
    for (int b = 0; b < 4; b++) {
        cudaMemsetAsync(out + ((size_t)(b * 8 + 7)) * frame, 0, frame * sizeof(float));
    }
}